// round 1
// baseline (speedup 1.0000x reference)
#include <cuda_runtime.h>
#include <math.h>

#define BB 4
#define SS 2048
#define DD 512
#define HH 8
#define DVV 64
#define NEG_INF_F (-1e30f)

// Scratch (device globals: allocation-free per harness rules)
__device__ float g_q[BB*HH*SS*DVV];
__device__ float g_k[BB*HH*SS*DVV];
__device__ float g_v[BB*HH*SS*DVV];
__device__ float g_heads[BB*SS*DD];

// ---------------------------------------------------------------------------
// Kernel 1: QKV projection.  q[b,h,s,e] = sum_d x[b,d,s]*W[h*64+e, d] + bias
// Tiled 128x128 output, K-tile 16.  grid: (S/128, D/128, B*3)
// ---------------------------------------------------------------------------
__global__ __launch_bounds__(256) void qkv_kernel(
    const float* __restrict__ x,
    const float* __restrict__ Wq, const float* __restrict__ bq,
    const float* __restrict__ Wk, const float* __restrict__ bk,
    const float* __restrict__ Wv, const float* __restrict__ bv)
{
    __shared__ float As[16][132];   // [k][m]   (x transposed on load)
    __shared__ float Bs[16][132];   // [k][n]

    int b = blockIdx.z / 3;
    int w = blockIdx.z % 3;
    const float* W    = (w == 0) ? Wq : (w == 1) ? Wk : Wv;
    const float* bias = (w == 0) ? bq : (w == 1) ? bk : bv;
    float* outp       = (w == 0) ? g_q : (w == 1) ? g_k : g_v;

    int m0 = blockIdx.x * 128;           // s tile
    int n0 = blockIdx.y * 128;           // output-feature tile
    int tid = threadIdx.x;
    int tx = tid & 15, ty = tid >> 4;

    const float* xb = x + (size_t)b * DD * SS;
    float acc[8][8];
#pragma unroll
    for (int i = 0; i < 8; i++)
#pragma unroll
        for (int j = 0; j < 8; j++) acc[i][j] = 0.f;

    for (int k0 = 0; k0 < DD; k0 += 16) {
        // A: As[dd][ss] = x[b][k0+dd][m0+ss]   (s contiguous -> coalesced)
        for (int i = tid; i < 16*128; i += 256) {
            int dd = i >> 7, ss = i & 127;
            As[dd][ss] = xb[(size_t)(k0 + dd) * SS + m0 + ss];
        }
        // B: Bs[dd][nn] = W[(n0+nn)*D + k0+dd]  (d contiguous 16-runs)
        for (int i = tid; i < 16*128; i += 256) {
            int nn = i >> 4, dd = i & 15;
            Bs[dd][nn] = W[(size_t)(n0 + nn) * DD + k0 + dd];
        }
        __syncthreads();
#pragma unroll
        for (int kk = 0; kk < 16; kk++) {
            float a[8], bb[8];
            *(float4*)&a[0]  = *(const float4*)&As[kk][ty*8];
            *(float4*)&a[4]  = *(const float4*)&As[kk][ty*8 + 4];
            *(float4*)&bb[0] = *(const float4*)&Bs[kk][tx*8];
            *(float4*)&bb[4] = *(const float4*)&Bs[kk][tx*8 + 4];
#pragma unroll
            for (int i = 0; i < 8; i++)
#pragma unroll
                for (int j = 0; j < 8; j++)
                    acc[i][j] += a[i] * bb[j];
        }
        __syncthreads();
    }

    // store into [b][h][s][e] layout
#pragma unroll
    for (int j = 0; j < 8; j++) {
        int n = n0 + tx*8 + j;
        float bv_ = bias[n];
        int h = n >> 6, e = n & 63;
#pragma unroll
        for (int i = 0; i < 8; i++) {
            int s = m0 + ty*8 + i;
            outp[(((size_t)b * HH + h) * SS + s) * DVV + e] = acc[i][j] + bv_;
        }
    }
}

// ---------------------------------------------------------------------------
// Kernel 2: attention with online softmax. One CTA = (b,h, 64 query rows).
// 64-key tiles.  256 threads: tx in [0,16) cols, ty in [0,16) row-groups of 4.
// ---------------------------------------------------------------------------
#define PAD 68
#define QS(r,c) Qs[(r)*PAD + (c)]
#define KS(r,c) Ks[(r)*PAD + (c)]
#define VS(r,c) Vs[(r)*PAD + (c)]
#define PS(r,c) Ps[(r)*PAD + (c)]

__global__ __launch_bounds__(256) void attn_kernel(const float* __restrict__ mask)
{
    extern __shared__ float sm[];
    float* Qs = sm;
    float* Ks = Qs + 64*PAD;
    float* Vs = Ks + 64*PAD;
    float* Ps = Vs + 64*PAD;
    float* mk = Ps + 64*PAD;   // 64 key-mask values

    int bh = blockIdx.y;             // b*H + h
    int b  = bh >> 3;
    int h  = bh & 7;
    int m0 = blockIdx.x * 64;
    int tid = threadIdx.x;
    int tx = tid & 15, ty = tid >> 4;
    const float scale = 0.125f;      // 1/sqrt(64)

    const float* qp = g_q + ((size_t)bh * SS + m0) * DVV;
    const float* kp = g_k + (size_t)bh * SS * DVV;
    const float* vp = g_v + (size_t)bh * SS * DVV;

    for (int i = tid; i < 64*64; i += 256) {
        int r = i >> 6, c = i & 63;
        QS(r, c) = qp[r * DVV + c];
    }

    float m_i[4], l_i[4], O[4][4];
#pragma unroll
    for (int i = 0; i < 4; i++) {
        m_i[i] = -INFINITY; l_i[i] = 0.f;
#pragma unroll
        for (int j = 0; j < 4; j++) O[i][j] = 0.f;
    }
    __syncthreads();

    for (int t0 = 0; t0 < SS; t0 += 64) {
        for (int i = tid; i < 64*64; i += 256) {
            int r = i >> 6, c = i & 63;
            KS(r, c) = kp[(size_t)(t0 + r) * DVV + c];
            VS(r, c) = vp[(size_t)(t0 + r) * DVV + c];
        }
        if (tid < 64) mk[tid] = mask[(size_t)b * SS + t0 + tid];
        __syncthreads();

        // scores: 4 rows x 4 cols per thread
        float sc[4][4];
#pragma unroll
        for (int i = 0; i < 4; i++)
#pragma unroll
            for (int j = 0; j < 4; j++) sc[i][j] = 0.f;

        for (int e = 0; e < 64; e += 4) {
            float4 q4[4], k4[4];
#pragma unroll
            for (int i = 0; i < 4; i++) q4[i] = *(const float4*)&QS(ty*4 + i, e);
#pragma unroll
            for (int j = 0; j < 4; j++) k4[j] = *(const float4*)&KS(tx*4 + j, e);
#pragma unroll
            for (int i = 0; i < 4; i++)
#pragma unroll
                for (int j = 0; j < 4; j++)
                    sc[i][j] += q4[i].x*k4[j].x + q4[i].y*k4[j].y
                              + q4[i].z*k4[j].z + q4[i].w*k4[j].w;
        }

        // scale + key mask:  s*m + (1-m)*NEG_INF
#pragma unroll
        for (int j = 0; j < 4; j++) {
            float mv = mk[tx*4 + j];
            float add = (1.f - mv) * NEG_INF_F;
#pragma unroll
            for (int i = 0; i < 4; i++)
                sc[i][j] = sc[i][j] * scale * mv + add;
        }

        // row max across this thread's cols, then across the 16-lane tx group
        float m_new[4], f[4], rsum[4];
#pragma unroll
        for (int i = 0; i < 4; i++) {
            float rm = fmaxf(fmaxf(sc[i][0], sc[i][1]), fmaxf(sc[i][2], sc[i][3]));
#pragma unroll
            for (int off = 8; off >= 1; off >>= 1)
                rm = fmaxf(rm, __shfl_xor_sync(0xffffffffu, rm, off));
            m_new[i] = fmaxf(m_i[i], rm);
            f[i] = __expf(m_i[i] - m_new[i]);
            float s_ = 0.f;
#pragma unroll
            for (int j = 0; j < 4; j++) {
                float p = __expf(sc[i][j] - m_new[i]);
                sc[i][j] = p;
                s_ += p;
            }
#pragma unroll
            for (int off = 8; off >= 1; off >>= 1)
                s_ += __shfl_xor_sync(0xffffffffu, s_, off);
            l_i[i] = l_i[i] * f[i] + s_;
            m_i[i] = m_new[i];
        }

        // stash P, rescale O
#pragma unroll
        for (int i = 0; i < 4; i++) {
#pragma unroll
            for (int j = 0; j < 4; j++) PS(ty*4 + i, tx*4 + j) = sc[i][j];
#pragma unroll
            for (int j = 0; j < 4; j++) O[i][j] *= f[i];
        }
        __syncthreads();

        // O += P @ V   (thread owns out cols tx*4..tx*4+3)
        for (int c = 0; c < 64; c += 4) {
            float p4[4][4];
#pragma unroll
            for (int i = 0; i < 4; i++) {
                float4 t = *(const float4*)&PS(ty*4 + i, c);
                p4[i][0] = t.x; p4[i][1] = t.y; p4[i][2] = t.z; p4[i][3] = t.w;
            }
#pragma unroll
            for (int cc = 0; cc < 4; cc++) {
                float4 v4 = *(const float4*)&VS(c + cc, tx*4);
#pragma unroll
                for (int i = 0; i < 4; i++) {
                    O[i][0] += p4[i][cc] * v4.x;
                    O[i][1] += p4[i][cc] * v4.y;
                    O[i][2] += p4[i][cc] * v4.z;
                    O[i][3] += p4[i][cc] * v4.w;
                }
            }
        }
        __syncthreads();
    }

    // finalize: divide by l, apply query mask, store into heads [b][s][h*64+e]
#pragma unroll
    for (int i = 0; i < 4; i++) {
        int s = m0 + ty*4 + i;
        float mq = mask[(size_t)b * SS + s];
        float inv = mq / l_i[i];
#pragma unroll
        for (int j = 0; j < 4; j++)
            g_heads[((size_t)b * SS + s) * DD + h * DVV + tx*4 + j] = O[i][j] * inv;
    }
}

// ---------------------------------------------------------------------------
// Kernel 3: output projection.  out[b,n,s] = sum_d heads[b,s,d]*W0[n,d] + b0[n]
// ---------------------------------------------------------------------------
__global__ __launch_bounds__(256) void proj_kernel(
    const float* __restrict__ W0, const float* __restrict__ b0,
    float* __restrict__ out)
{
    __shared__ float As[16][132];   // [k][m] (heads transposed on load)
    __shared__ float Bs[16][132];   // [k][n]

    int b  = blockIdx.z;
    int m0 = blockIdx.x * 128;      // s tile
    int n0 = blockIdx.y * 128;      // n tile
    int tid = threadIdx.x;
    int tx = tid & 15, ty = tid >> 4;

    const float* hb = g_heads + (size_t)b * SS * DD;
    float acc[8][8];
#pragma unroll
    for (int i = 0; i < 8; i++)
#pragma unroll
        for (int j = 0; j < 8; j++) acc[i][j] = 0.f;

    for (int k0 = 0; k0 < DD; k0 += 16) {
        for (int i = tid; i < 16*128; i += 256) {
            int ss = i >> 4, dd = i & 15;
            As[dd][ss] = hb[(size_t)(m0 + ss) * DD + k0 + dd];
        }
        for (int i = tid; i < 16*128; i += 256) {
            int nn = i >> 4, dd = i & 15;
            Bs[dd][nn] = W0[(size_t)(n0 + nn) * DD + k0 + dd];
        }
        __syncthreads();
#pragma unroll
        for (int kk = 0; kk < 16; kk++) {
            float a[8], bb[8];
            *(float4*)&a[0]  = *(const float4*)&As[kk][ty*8];
            *(float4*)&a[4]  = *(const float4*)&As[kk][ty*8 + 4];
            *(float4*)&bb[0] = *(const float4*)&Bs[kk][tx*8];
            *(float4*)&bb[4] = *(const float4*)&Bs[kk][tx*8 + 4];
#pragma unroll
            for (int i = 0; i < 8; i++)
#pragma unroll
                for (int j = 0; j < 8; j++)
                    acc[i][j] += a[i] * bb[j];
        }
        __syncthreads();
    }

#pragma unroll
    for (int j = 0; j < 8; j++) {
        int n = n0 + tx*8 + j;
        float bv_ = b0[n];
#pragma unroll
        for (int i = 0; i < 8; i++) {
            int s = m0 + ty*8 + i;
            out[((size_t)b * DD + n) * SS + s] = acc[i][j] + bv_;
        }
    }
}

// ---------------------------------------------------------------------------
extern "C" void kernel_launch(void* const* d_in, const int* in_sizes, int n_in,
                              void* d_out, int out_size)
{
    const float* x    = (const float*)d_in[0];
    const float* mask = (const float*)d_in[1];
    const float* Wq   = (const float*)d_in[2];
    const float* bq   = (const float*)d_in[3];
    const float* Wk   = (const float*)d_in[4];
    const float* bk   = (const float*)d_in[5];
    const float* Wv   = (const float*)d_in[6];
    const float* bv   = (const float*)d_in[7];
    const float* W0   = (const float*)d_in[8];
    const float* b0   = (const float*)d_in[9];
    float* out = (float*)d_out;

    const int attn_smem = (4 * 64 * PAD + 64) * (int)sizeof(float);  // 69888 B
    cudaFuncSetAttribute(attn_kernel,
                         cudaFuncAttributeMaxDynamicSharedMemorySize, attn_smem);

    qkv_kernel<<<dim3(SS/128, DD/128, BB*3), 256>>>(x, Wq, bq, Wk, bk, Wv, bv);
    attn_kernel<<<dim3(SS/64, BB*HH), 256, attn_smem>>>(mask);
    proj_kernel<<<dim3(SS/128, DD/128, BB), 256>>>(W0, b0, out);
}

// round 2
// speedup vs baseline: 3.6289x; 3.6289x over previous
#include <cuda_runtime.h>
#include <math.h>

#define BB 4
#define SS 2048
#define DD 512
#define HH 8
#define DVV 64
#define NEG_INF_F (-1e30f)

// Scratch (device globals: allocation-free per harness rules)
__device__ float g_q[BB*HH*SS*DVV];
__device__ float g_k[BB*HH*SS*DVV];
__device__ float g_vT[BB*HH*DVV*SS];   // V stored transposed: [b,h,e,s]
__device__ float g_heads[BB*SS*DD];

__device__ __forceinline__ unsigned f2tf(float f) {
    unsigned u;
    asm("cvt.rna.tf32.f32 %0, %1;" : "=r"(u) : "f"(f));
    return u;
}

__device__ __forceinline__ void mma8(float* d, const unsigned* a, const unsigned* b) {
    asm volatile(
        "mma.sync.aligned.m16n8k8.row.col.f32.tf32.tf32.f32 "
        "{%0,%1,%2,%3},{%4,%5,%6,%7},{%8,%9},{%0,%1,%2,%3};\n"
        : "+f"(d[0]), "+f"(d[1]), "+f"(d[2]), "+f"(d[3])
        : "r"(a[0]), "r"(a[1]), "r"(a[2]), "r"(a[3]), "r"(b[0]), "r"(b[1]));
}

// ---------------------------------------------------------------------------
// Kernel 1: QKV projection via tf32 mma. C = x^T @ W^T + bias.
// A = x^T (k-major natural in x), B = W [n][k] (natural col-major).
// BM=128, BN=128, BK=32. 8 warps in 2(M)x4(N) grid, warp tile 64x32.
// q,k stored [b,h,s,e]; v stored transposed [b,h,e,s].
// ---------------------------------------------------------------------------
__global__ __launch_bounds__(256) void qkv_mma(
    const float* __restrict__ x,
    const float* __restrict__ Wq, const float* __restrict__ bq,
    const float* __restrict__ Wk, const float* __restrict__ bk,
    const float* __restrict__ Wv, const float* __restrict__ bv)
{
    __shared__ float As[32][136];   // [k][m]
    __shared__ float Bs[128][40];   // [n][k]

    int b = blockIdx.z / 3, w = blockIdx.z % 3;
    const float* W    = (w == 0) ? Wq : (w == 1) ? Wk : Wv;
    const float* bias = (w == 0) ? bq : (w == 1) ? bk : bv;

    int m0 = blockIdx.x * 128, n0 = blockIdx.y * 128;
    int tid = threadIdx.x, lane = tid & 31, warp = tid >> 5;
    int wm = warp & 1, wn = warp >> 1;
    int gid = lane >> 2, tig = lane & 3;
    const float* xb = x + (size_t)b * DD * SS;

    float acc[4][4][4];
#pragma unroll
    for (int mt = 0; mt < 4; mt++)
#pragma unroll
        for (int nt = 0; nt < 4; nt++)
#pragma unroll
            for (int j = 0; j < 4; j++) acc[mt][nt][j] = 0.f;

    for (int k0 = 0; k0 < DD; k0 += 32) {
#pragma unroll
        for (int i = tid; i < 32 * 32; i += 256) {      // 32 k-rows x 32 float4
            int kk = i >> 5, m4 = i & 31;
            float4 v = *(const float4*)&xb[(size_t)(k0 + kk) * SS + m0 + m4 * 4];
            v.x = __uint_as_float(f2tf(v.x)); v.y = __uint_as_float(f2tf(v.y));
            v.z = __uint_as_float(f2tf(v.z)); v.w = __uint_as_float(f2tf(v.w));
            *(float4*)&As[kk][m4 * 4] = v;
        }
#pragma unroll
        for (int i = tid; i < 128 * 8; i += 256) {      // 128 n-rows x 8 float4
            int nn = i >> 3, k4 = i & 7;
            float4 v = *(const float4*)&W[(size_t)(n0 + nn) * DD + k0 + k4 * 4];
            v.x = __uint_as_float(f2tf(v.x)); v.y = __uint_as_float(f2tf(v.y));
            v.z = __uint_as_float(f2tf(v.z)); v.w = __uint_as_float(f2tf(v.w));
            *(float4*)&Bs[nn][k4 * 4] = v;
        }
        __syncthreads();
#pragma unroll
        for (int ks = 0; ks < 32; ks += 8) {
            unsigned af[4][4], bf[4][2];
#pragma unroll
            for (int mt = 0; mt < 4; mt++) {
                int m = wm * 64 + mt * 16 + gid;
                af[mt][0] = __float_as_uint(As[ks + tig][m]);
                af[mt][1] = __float_as_uint(As[ks + tig][m + 8]);
                af[mt][2] = __float_as_uint(As[ks + 4 + tig][m]);
                af[mt][3] = __float_as_uint(As[ks + 4 + tig][m + 8]);
            }
#pragma unroll
            for (int nt = 0; nt < 4; nt++) {
                int n = wn * 32 + nt * 8 + gid;
                bf[nt][0] = __float_as_uint(Bs[n][ks + tig]);
                bf[nt][1] = __float_as_uint(Bs[n][ks + 4 + tig]);
            }
#pragma unroll
            for (int mt = 0; mt < 4; mt++)
#pragma unroll
                for (int nt = 0; nt < 4; nt++)
                    mma8(acc[mt][nt], af[mt], bf[nt]);
        }
        __syncthreads();
    }

    if (w < 2) {
        float* outp = (w == 0) ? g_q : g_k;
#pragma unroll
        for (int mt = 0; mt < 4; mt++)
#pragma unroll
            for (int nt = 0; nt < 4; nt++) {
                int n = n0 + wn * 32 + nt * 8 + tig * 2;
                int r = m0 + wm * 64 + mt * 16 + gid;
                int h = n >> 6, e = n & 63;
                float b0v = bias[n], b1v = bias[n + 1];
                size_t base = (((size_t)b * HH + h) * SS);
                float2 v0, v1;
                v0.x = __uint_as_float(f2tf(acc[mt][nt][0] + b0v));
                v0.y = __uint_as_float(f2tf(acc[mt][nt][1] + b1v));
                v1.x = __uint_as_float(f2tf(acc[mt][nt][2] + b0v));
                v1.y = __uint_as_float(f2tf(acc[mt][nt][3] + b1v));
                *(float2*)&outp[(base + r) * DVV + e]     = v0;
                *(float2*)&outp[(base + r + 8) * DVV + e] = v1;
            }
    } else {
        // V transposed: g_vT[((b*H+h)*64 + e) * S + s]
#pragma unroll
        for (int mt = 0; mt < 4; mt++)
#pragma unroll
            for (int nt = 0; nt < 4; nt++) {
                int n = n0 + wn * 32 + nt * 8 + tig * 2;
                int r = m0 + wm * 64 + mt * 16 + gid;
                int h = n >> 6, e = n & 63;
                float b0v = bias[n], b1v = bias[n + 1];
                size_t r0 = (((size_t)b * HH + h) * DVV + e) * SS;
                size_t r1 = r0 + SS;
                g_vT[r0 + r]     = __uint_as_float(f2tf(acc[mt][nt][0] + b0v));
                g_vT[r1 + r]     = __uint_as_float(f2tf(acc[mt][nt][1] + b1v));
                g_vT[r0 + r + 8] = __uint_as_float(f2tf(acc[mt][nt][2] + b0v));
                g_vT[r1 + r + 8] = __uint_as_float(f2tf(acc[mt][nt][3] + b1v));
            }
    }
}

// ---------------------------------------------------------------------------
// Kernel 2: flash attention with tf32 mma.
// CTA = (b,h, 128 q rows). Key tile 128. 8 warps, each owns 16 q rows fully.
// ---------------------------------------------------------------------------
#define SQK 72
#define SVT 136
#define SPP 132
#define ATTN_SMEM ((128*SQK + 128*SQK + 64*SVT + 128*SPP + 128) * 4)

extern __shared__ float smx[];

__global__ __launch_bounds__(256) void attn_mma(const float* __restrict__ mask)
{
    float* Qs = smx;                 // [128][72]  A (row-major)
    float* Ks = Qs + 128 * SQK;      // [128][72]  B col-major ([key][e])
    float* Vs = Ks + 128 * SQK;      // [64][136]  B col-major ([e][key])
    float* Ps = Vs + 64 * SVT;       // [128][132] A (row-major)
    float* mk = Ps + 128 * SPP;      // [128]

    int bh = blockIdx.y, b = bh >> 3, h = bh & 7;
    int m0 = blockIdx.x * 128;
    int tid = threadIdx.x, lane = tid & 31, w = tid >> 5;
    int gid = lane >> 2, tig = lane & 3;

    const float* qp = g_q  + ((size_t)bh * SS + m0) * DVV;
    const float* kp = g_k  + (size_t)bh * SS * DVV;
    const float* vp = g_vT + (size_t)bh * DVV * SS;

#pragma unroll
    for (int i = tid; i < 128 * 16; i += 256) {
        int r = i >> 4, e4 = i & 15;
        *(float4*)&Qs[r * SQK + e4 * 4] = *(const float4*)&qp[r * DVV + e4 * 4];
    }

    float m_i[2] = {-INFINITY, -INFINITY}, l_i[2] = {0.f, 0.f};
    float oacc[8][4];
#pragma unroll
    for (int nt = 0; nt < 8; nt++)
#pragma unroll
        for (int j = 0; j < 4; j++) oacc[nt][j] = 0.f;

    int r0 = w * 16 + gid;

    for (int t0 = 0; t0 < SS; t0 += 128) {
#pragma unroll
        for (int i = tid; i < 128 * 16; i += 256) {
            int r = i >> 4, e4 = i & 15;
            *(float4*)&Ks[r * SQK + e4 * 4] =
                *(const float4*)&kp[(size_t)(t0 + r) * DVV + e4 * 4];
        }
#pragma unroll
        for (int i = tid; i < 64 * 32; i += 256) {
            int e = i >> 5, k4 = i & 31;
            *(float4*)&Vs[e * SVT + k4 * 4] =
                *(const float4*)&vp[(size_t)e * SS + t0 + k4 * 4];
        }
        if (tid < 128) mk[tid] = mask[(size_t)b * SS + t0 + tid];
        __syncthreads();

        // ---- S = Q @ K^T ----
        float sacc[16][4];
#pragma unroll
        for (int nt = 0; nt < 16; nt++)
#pragma unroll
            for (int j = 0; j < 4; j++) sacc[nt][j] = 0.f;

#pragma unroll
        for (int kt = 0; kt < 8; kt++) {
            unsigned af[4];
            af[0] = __float_as_uint(Qs[r0 * SQK + kt * 8 + tig]);
            af[1] = __float_as_uint(Qs[(r0 + 8) * SQK + kt * 8 + tig]);
            af[2] = __float_as_uint(Qs[r0 * SQK + kt * 8 + 4 + tig]);
            af[3] = __float_as_uint(Qs[(r0 + 8) * SQK + kt * 8 + 4 + tig]);
#pragma unroll
            for (int nt = 0; nt < 16; nt++) {
                unsigned bf[2];
                bf[0] = __float_as_uint(Ks[(nt * 8 + gid) * SQK + kt * 8 + tig]);
                bf[1] = __float_as_uint(Ks[(nt * 8 + gid) * SQK + kt * 8 + 4 + tig]);
                mma8(sacc[nt], af, bf);
            }
        }

        // ---- masked online softmax (each warp owns full rows) ----
        float rm0 = -INFINITY, rm1 = -INFINITY;
#pragma unroll
        for (int nt = 0; nt < 16; nt++) {
            float mv0 = mk[nt * 8 + tig * 2], mv1 = mk[nt * 8 + tig * 2 + 1];
            float ad0 = (1.f - mv0) * NEG_INF_F, ad1 = (1.f - mv1) * NEG_INF_F;
            sacc[nt][0] = sacc[nt][0] * 0.125f * mv0 + ad0;
            sacc[nt][1] = sacc[nt][1] * 0.125f * mv1 + ad1;
            sacc[nt][2] = sacc[nt][2] * 0.125f * mv0 + ad0;
            sacc[nt][3] = sacc[nt][3] * 0.125f * mv1 + ad1;
            rm0 = fmaxf(rm0, fmaxf(sacc[nt][0], sacc[nt][1]));
            rm1 = fmaxf(rm1, fmaxf(sacc[nt][2], sacc[nt][3]));
        }
        rm0 = fmaxf(rm0, __shfl_xor_sync(0xffffffffu, rm0, 1));
        rm0 = fmaxf(rm0, __shfl_xor_sync(0xffffffffu, rm0, 2));
        rm1 = fmaxf(rm1, __shfl_xor_sync(0xffffffffu, rm1, 1));
        rm1 = fmaxf(rm1, __shfl_xor_sync(0xffffffffu, rm1, 2));

        float mn0 = fmaxf(m_i[0], rm0), mn1 = fmaxf(m_i[1], rm1);
        float f0 = __expf(m_i[0] - mn0), f1 = __expf(m_i[1] - mn1);
        float s0 = 0.f, s1 = 0.f;
#pragma unroll
        for (int nt = 0; nt < 16; nt++) {
            sacc[nt][0] = __expf(sacc[nt][0] - mn0);
            sacc[nt][1] = __expf(sacc[nt][1] - mn0);
            sacc[nt][2] = __expf(sacc[nt][2] - mn1);
            sacc[nt][3] = __expf(sacc[nt][3] - mn1);
            s0 += sacc[nt][0] + sacc[nt][1];
            s1 += sacc[nt][2] + sacc[nt][3];
        }
        s0 += __shfl_xor_sync(0xffffffffu, s0, 1);
        s0 += __shfl_xor_sync(0xffffffffu, s0, 2);
        s1 += __shfl_xor_sync(0xffffffffu, s1, 1);
        s1 += __shfl_xor_sync(0xffffffffu, s1, 2);
        l_i[0] = l_i[0] * f0 + s0;  m_i[0] = mn0;
        l_i[1] = l_i[1] * f1 + s1;  m_i[1] = mn1;

#pragma unroll
        for (int nt = 0; nt < 8; nt++) {
            oacc[nt][0] *= f0; oacc[nt][1] *= f0;
            oacc[nt][2] *= f1; oacc[nt][3] *= f1;
        }

        // stash P (tf32-rounded) into this warp's private rows
#pragma unroll
        for (int nt = 0; nt < 16; nt++) {
            int c = nt * 8 + tig * 2;
            Ps[r0 * SPP + c]           = __uint_as_float(f2tf(sacc[nt][0]));
            Ps[r0 * SPP + c + 1]       = __uint_as_float(f2tf(sacc[nt][1]));
            Ps[(r0 + 8) * SPP + c]     = __uint_as_float(f2tf(sacc[nt][2]));
            Ps[(r0 + 8) * SPP + c + 1] = __uint_as_float(f2tf(sacc[nt][3]));
        }
        __syncwarp();

        // ---- O += P @ V ----
#pragma unroll
        for (int kt = 0; kt < 16; kt++) {
            unsigned af[4];
            af[0] = __float_as_uint(Ps[r0 * SPP + kt * 8 + tig]);
            af[1] = __float_as_uint(Ps[(r0 + 8) * SPP + kt * 8 + tig]);
            af[2] = __float_as_uint(Ps[r0 * SPP + kt * 8 + 4 + tig]);
            af[3] = __float_as_uint(Ps[(r0 + 8) * SPP + kt * 8 + 4 + tig]);
#pragma unroll
            for (int nt = 0; nt < 8; nt++) {
                unsigned bf[2];
                bf[0] = __float_as_uint(Vs[(nt * 8 + gid) * SVT + kt * 8 + tig]);
                bf[1] = __float_as_uint(Vs[(nt * 8 + gid) * SVT + kt * 8 + 4 + tig]);
                mma8(oacc[nt], af, bf);
            }
        }
        __syncthreads();
    }

    // epilogue: normalize, query-mask, store heads [b][s][h*64+e] (tf32-rounded)
    int s0r = m0 + r0, s1r = s0r + 8;
    float q0 = mask[(size_t)b * SS + s0r] / l_i[0];
    float q1 = mask[(size_t)b * SS + s1r] / l_i[1];
#pragma unroll
    for (int nt = 0; nt < 8; nt++) {
        int e = h * DVV + nt * 8 + tig * 2;
        float2 v0, v1;
        v0.x = __uint_as_float(f2tf(oacc[nt][0] * q0));
        v0.y = __uint_as_float(f2tf(oacc[nt][1] * q0));
        v1.x = __uint_as_float(f2tf(oacc[nt][2] * q1));
        v1.y = __uint_as_float(f2tf(oacc[nt][3] * q1));
        *(float2*)&g_heads[((size_t)b * SS + s0r) * DD + e] = v0;
        *(float2*)&g_heads[((size_t)b * SS + s1r) * DD + e] = v1;
    }
}

// ---------------------------------------------------------------------------
// Kernel 3: output projection via tf32 mma. out[b,n,s] = heads[b,s,:]·W0[n,:]+b0
// A = heads (row-major natural), B = W0 [n][k] (natural col-major).
// ---------------------------------------------------------------------------
__global__ __launch_bounds__(256) void proj_mma(
    const float* __restrict__ W0, const float* __restrict__ b0,
    float* __restrict__ out)
{
    __shared__ float As[128][40];   // [m][k]
    __shared__ float Bs[128][40];   // [n][k]

    int b = blockIdx.z;
    int m0 = blockIdx.x * 128, n0 = blockIdx.y * 128;
    int tid = threadIdx.x, lane = tid & 31, warp = tid >> 5;
    int wm = warp & 1, wn = warp >> 1;
    int gid = lane >> 2, tig = lane & 3;
    const float* hb = g_heads + (size_t)b * SS * DD;

    float acc[4][4][4];
#pragma unroll
    for (int mt = 0; mt < 4; mt++)
#pragma unroll
        for (int nt = 0; nt < 4; nt++)
#pragma unroll
            for (int j = 0; j < 4; j++) acc[mt][nt][j] = 0.f;

    for (int k0 = 0; k0 < DD; k0 += 32) {
#pragma unroll
        for (int i = tid; i < 128 * 8; i += 256) {
            int mm = i >> 3, k4 = i & 7;
            *(float4*)&As[mm][k4 * 4] =
                *(const float4*)&hb[(size_t)(m0 + mm) * DD + k0 + k4 * 4];
        }
#pragma unroll
        for (int i = tid; i < 128 * 8; i += 256) {
            int nn = i >> 3, k4 = i & 7;
            float4 v = *(const float4*)&W0[(size_t)(n0 + nn) * DD + k0 + k4 * 4];
            v.x = __uint_as_float(f2tf(v.x)); v.y = __uint_as_float(f2tf(v.y));
            v.z = __uint_as_float(f2tf(v.z)); v.w = __uint_as_float(f2tf(v.w));
            *(float4*)&Bs[nn][k4 * 4] = v;
        }
        __syncthreads();
#pragma unroll
        for (int ks = 0; ks < 32; ks += 8) {
            unsigned af[4][4], bf[4][2];
#pragma unroll
            for (int mt = 0; mt < 4; mt++) {
                int m = wm * 64 + mt * 16 + gid;
                af[mt][0] = __float_as_uint(As[m][ks + tig]);
                af[mt][1] = __float_as_uint(As[m + 8][ks + tig]);
                af[mt][2] = __float_as_uint(As[m][ks + 4 + tig]);
                af[mt][3] = __float_as_uint(As[m + 8][ks + 4 + tig]);
            }
#pragma unroll
            for (int nt = 0; nt < 4; nt++) {
                int n = wn * 32 + nt * 8 + gid;
                bf[nt][0] = __float_as_uint(Bs[n][ks + tig]);
                bf[nt][1] = __float_as_uint(Bs[n][ks + 4 + tig]);
            }
#pragma unroll
            for (int mt = 0; mt < 4; mt++)
#pragma unroll
                for (int nt = 0; nt < 4; nt++)
                    mma8(acc[mt][nt], af[mt], bf[nt]);
        }
        __syncthreads();
    }

#pragma unroll
    for (int mt = 0; mt < 4; mt++)
#pragma unroll
        for (int nt = 0; nt < 4; nt++) {
            int n = n0 + wn * 32 + nt * 8 + tig * 2;
            int r = m0 + wm * 64 + mt * 16 + gid;
            float b0v = b0[n], b1v = b0[n + 1];
            size_t c0 = ((size_t)b * DD + n) * SS;
            size_t c1 = c0 + SS;
            out[c0 + r]     = acc[mt][nt][0] + b0v;
            out[c1 + r]     = acc[mt][nt][1] + b1v;
            out[c0 + r + 8] = acc[mt][nt][2] + b0v;
            out[c1 + r + 8] = acc[mt][nt][3] + b1v;
        }
}

// ---------------------------------------------------------------------------
extern "C" void kernel_launch(void* const* d_in, const int* in_sizes, int n_in,
                              void* d_out, int out_size)
{
    const float* x    = (const float*)d_in[0];
    const float* mask = (const float*)d_in[1];
    const float* Wq   = (const float*)d_in[2];
    const float* bq   = (const float*)d_in[3];
    const float* Wk   = (const float*)d_in[4];
    const float* bk   = (const float*)d_in[5];
    const float* Wv   = (const float*)d_in[6];
    const float* bv   = (const float*)d_in[7];
    const float* W0   = (const float*)d_in[8];
    const float* b0   = (const float*)d_in[9];
    float* out = (float*)d_out;

    cudaFuncSetAttribute(attn_mma,
                         cudaFuncAttributeMaxDynamicSharedMemorySize, ATTN_SMEM);

    qkv_mma<<<dim3(SS/128, DD/128, BB*3), 256>>>(x, Wq, bq, Wk, bk, Wv, bv);
    attn_mma<<<dim3(SS/128, BB*HH), 256, ATTN_SMEM>>>(mask);
    proj_mma<<<dim3(SS/128, DD/128, BB), 256>>>(W0, b0, out);
}

// round 3
// speedup vs baseline: 4.6140x; 1.2715x over previous
#include <cuda_runtime.h>
#include <math.h>

#define BB 4
#define SS 2048
#define DD 512
#define HH 8
#define DVV 64
#define NEG_INF_F (-1e30f)

// Scratch (device globals: allocation-free per harness rules)
__device__ float g_q[BB*HH*SS*DVV];
__device__ float g_k[BB*HH*SS*DVV];
__device__ float g_vT[BB*HH*DVV*SS];   // V stored transposed: [b,h,e,s]
__device__ float g_heads[BB*SS*DD];

__device__ __forceinline__ unsigned f2tf(float f) {
    unsigned u;
    asm("cvt.rna.tf32.f32 %0, %1;" : "=r"(u) : "f"(f));
    return u;
}

__device__ __forceinline__ float ex2(float x) {
    float y;
    asm("ex2.approx.ftz.f32 %0, %1;" : "=f"(y) : "f"(x));
    return y;
}

__device__ __forceinline__ void mma8(float* d, const unsigned* a, const unsigned* b) {
    asm volatile(
        "mma.sync.aligned.m16n8k8.row.col.f32.tf32.tf32.f32 "
        "{%0,%1,%2,%3},{%4,%5,%6,%7},{%8,%9},{%0,%1,%2,%3};\n"
        : "+f"(d[0]), "+f"(d[1]), "+f"(d[2]), "+f"(d[3])
        : "r"(a[0]), "r"(a[1]), "r"(a[2]), "r"(a[3]), "r"(b[0]), "r"(b[1]));
}

// ---------------------------------------------------------------------------
// Kernel 1: QKV projection via tf32 mma (unchanged from R2).
// ---------------------------------------------------------------------------
__global__ __launch_bounds__(256) void qkv_mma(
    const float* __restrict__ x,
    const float* __restrict__ Wq, const float* __restrict__ bq,
    const float* __restrict__ Wk, const float* __restrict__ bk,
    const float* __restrict__ Wv, const float* __restrict__ bv)
{
    __shared__ float As[32][136];   // [k][m]
    __shared__ float Bs[128][40];   // [n][k]

    int b = blockIdx.z / 3, w = blockIdx.z % 3;
    const float* W    = (w == 0) ? Wq : (w == 1) ? Wk : Wv;
    const float* bias = (w == 0) ? bq : (w == 1) ? bk : bv;

    int m0 = blockIdx.x * 128, n0 = blockIdx.y * 128;
    int tid = threadIdx.x, lane = tid & 31, warp = tid >> 5;
    int wm = warp & 1, wn = warp >> 1;
    int gid = lane >> 2, tig = lane & 3;
    const float* xb = x + (size_t)b * DD * SS;

    float acc[4][4][4];
#pragma unroll
    for (int mt = 0; mt < 4; mt++)
#pragma unroll
        for (int nt = 0; nt < 4; nt++)
#pragma unroll
            for (int j = 0; j < 4; j++) acc[mt][nt][j] = 0.f;

    for (int k0 = 0; k0 < DD; k0 += 32) {
#pragma unroll
        for (int i = tid; i < 32 * 32; i += 256) {
            int kk = i >> 5, m4 = i & 31;
            float4 v = *(const float4*)&xb[(size_t)(k0 + kk) * SS + m0 + m4 * 4];
            v.x = __uint_as_float(f2tf(v.x)); v.y = __uint_as_float(f2tf(v.y));
            v.z = __uint_as_float(f2tf(v.z)); v.w = __uint_as_float(f2tf(v.w));
            *(float4*)&As[kk][m4 * 4] = v;
        }
#pragma unroll
        for (int i = tid; i < 128 * 8; i += 256) {
            int nn = i >> 3, k4 = i & 7;
            float4 v = *(const float4*)&W[(size_t)(n0 + nn) * DD + k0 + k4 * 4];
            v.x = __uint_as_float(f2tf(v.x)); v.y = __uint_as_float(f2tf(v.y));
            v.z = __uint_as_float(f2tf(v.z)); v.w = __uint_as_float(f2tf(v.w));
            *(float4*)&Bs[nn][k4 * 4] = v;
        }
        __syncthreads();
#pragma unroll
        for (int ks = 0; ks < 32; ks += 8) {
            unsigned af[4][4], bf[4][2];
#pragma unroll
            for (int mt = 0; mt < 4; mt++) {
                int m = wm * 64 + mt * 16 + gid;
                af[mt][0] = __float_as_uint(As[ks + tig][m]);
                af[mt][1] = __float_as_uint(As[ks + tig][m + 8]);
                af[mt][2] = __float_as_uint(As[ks + 4 + tig][m]);
                af[mt][3] = __float_as_uint(As[ks + 4 + tig][m + 8]);
            }
#pragma unroll
            for (int nt = 0; nt < 4; nt++) {
                int n = wn * 32 + nt * 8 + gid;
                bf[nt][0] = __float_as_uint(Bs[n][ks + tig]);
                bf[nt][1] = __float_as_uint(Bs[n][ks + 4 + tig]);
            }
#pragma unroll
            for (int mt = 0; mt < 4; mt++)
#pragma unroll
                for (int nt = 0; nt < 4; nt++)
                    mma8(acc[mt][nt], af[mt], bf[nt]);
        }
        __syncthreads();
    }

    if (w < 2) {
        float* outp = (w == 0) ? g_q : g_k;
#pragma unroll
        for (int mt = 0; mt < 4; mt++)
#pragma unroll
            for (int nt = 0; nt < 4; nt++) {
                int n = n0 + wn * 32 + nt * 8 + tig * 2;
                int r = m0 + wm * 64 + mt * 16 + gid;
                int h = n >> 6, e = n & 63;
                float b0v = bias[n], b1v = bias[n + 1];
                size_t base = (((size_t)b * HH + h) * SS);
                float2 v0, v1;
                v0.x = __uint_as_float(f2tf(acc[mt][nt][0] + b0v));
                v0.y = __uint_as_float(f2tf(acc[mt][nt][1] + b1v));
                v1.x = __uint_as_float(f2tf(acc[mt][nt][2] + b0v));
                v1.y = __uint_as_float(f2tf(acc[mt][nt][3] + b1v));
                *(float2*)&outp[(base + r) * DVV + e]     = v0;
                *(float2*)&outp[(base + r + 8) * DVV + e] = v1;
            }
    } else {
#pragma unroll
        for (int mt = 0; mt < 4; mt++)
#pragma unroll
            for (int nt = 0; nt < 4; nt++) {
                int n = n0 + wn * 32 + nt * 8 + tig * 2;
                int r = m0 + wm * 64 + mt * 16 + gid;
                int h = n >> 6, e = n & 63;
                float b0v = bias[n], b1v = bias[n + 1];
                size_t r0 = (((size_t)b * HH + h) * DVV + e) * SS;
                size_t r1 = r0 + SS;
                g_vT[r0 + r]     = __uint_as_float(f2tf(acc[mt][nt][0] + b0v));
                g_vT[r1 + r]     = __uint_as_float(f2tf(acc[mt][nt][1] + b1v));
                g_vT[r0 + r + 8] = __uint_as_float(f2tf(acc[mt][nt][2] + b0v));
                g_vT[r1 + r + 8] = __uint_as_float(f2tf(acc[mt][nt][3] + b1v));
            }
    }
}

// ---------------------------------------------------------------------------
// Kernel 2: flash attention, fragment-native smem layouts.
// CTA = (b,h, 128 q rows). Key tile 128. 8 warps x 16 q rows.
//   Qf: float4[w][kt8][gid8][tig4]              (conflict-free LDS.128)
//   Kf: float2[(nt*8+kt)][gid][tig], pad 33     (conflict-free LDS.64)
//   Vf: float2[(nt*16+kt)][gid][tig], pad 33    (conflict-free LDS.64)
//   Ps: [128][132] scalar (conflict-free both directions)
// Softmax in log2 domain (ex2.approx, scale folded).
// ---------------------------------------------------------------------------
#define SPP 132
#define QF_FLOATS  (2048 * 4)        // 8192
#define KF_FLOATS  (128 * 33 * 2)    // 8448
#define VF_FLOATS  (128 * 33 * 2)    // 8448
#define PS_FLOATS  (128 * SPP)       // 16896
#define ATTN_SMEM  ((QF_FLOATS + KF_FLOATS + VF_FLOATS + PS_FLOATS + 128) * 4)

#define SCALE2 0.1803368801111244f   /* 0.125 * log2(e) */
#define NEG2F  (-1.442695e30f)       /* NEG_INF * log2(e) */

extern __shared__ float smx[];

__global__ __launch_bounds__(256) void attn_mma(const float* __restrict__ mask)
{
    float4* Qf = (float4*)smx;
    float2* Kf = (float2*)(smx + QF_FLOATS);
    float2* Vf = (float2*)(smx + QF_FLOATS + KF_FLOATS);
    float*  Ps = smx + QF_FLOATS + KF_FLOATS + VF_FLOATS;
    float*  mk = Ps + PS_FLOATS;

    int bh = blockIdx.y, b = bh >> 3, h = bh & 7;
    int m0 = blockIdx.x * 128;
    int tid = threadIdx.x, lane = tid & 31, w = tid >> 5;
    int gid = lane >> 2, tig = lane & 3;

    const float* qp = g_q  + ((size_t)bh * SS + m0) * DVV;
    const float* kp = g_k  + (size_t)bh * SS * DVV;
    const float* vp = g_vT + (size_t)bh * DVV * SS;

    // Q -> fragment layout (once). idx = ((ww*8+kt)*8+gid)*4+tig == i
#pragma unroll
    for (int i = tid; i < 2048; i += 256) {
        int ftig = i & 3, fgid = (i >> 2) & 7, fkt = (i >> 5) & 7, fw = i >> 8;
        int r = fw * 16 + fgid, c = fkt * 8 + ftig;
        float4 v;
        v.x = qp[r * DVV + c];
        v.y = qp[(r + 8) * DVV + c];
        v.z = qp[r * DVV + c + 4];
        v.w = qp[(r + 8) * DVV + c + 4];
        Qf[i] = v;
    }

    float m_i[2] = {-INFINITY, -INFINITY}, l_i[2] = {0.f, 0.f};
    float oacc[8][4];
#pragma unroll
    for (int nt = 0; nt < 8; nt++)
#pragma unroll
        for (int j = 0; j < 4; j++) oacc[nt][j] = 0.f;

    int r0 = w * 16 + gid;

    for (int t0 = 0; t0 < SS; t0 += 128) {
        // ---- fill K fragments ----
#pragma unroll
        for (int i = tid; i < 1024; i += 256) {
            int fkt = i & 7, n = i >> 3;
            const float* kr = kp + (size_t)(t0 + n) * DVV + fkt * 8;
            float4 lo = *(const float4*)kr, hi = *(const float4*)(kr + 4);
            float2* dst = Kf + ((n >> 3) * 8 + fkt) * 33 + (n & 7) * 4;
            dst[0] = make_float2(lo.x, hi.x);
            dst[1] = make_float2(lo.y, hi.y);
            dst[2] = make_float2(lo.z, hi.z);
            dst[3] = make_float2(lo.w, hi.w);
        }
        // ---- fill V fragments ----
#pragma unroll
        for (int i = tid; i < 1024; i += 256) {
            int fkt = i & 15, e = i >> 4;
            const float* vr = vp + (size_t)e * SS + t0 + fkt * 8;
            float4 lo = *(const float4*)vr, hi = *(const float4*)(vr + 4);
            float2* dst = Vf + ((e >> 3) * 16 + fkt) * 33 + (e & 7) * 4;
            dst[0] = make_float2(lo.x, hi.x);
            dst[1] = make_float2(lo.y, hi.y);
            dst[2] = make_float2(lo.z, hi.z);
            dst[3] = make_float2(lo.w, hi.w);
        }
        if (tid < 128) mk[tid] = mask[(size_t)b * SS + t0 + tid];
        __syncthreads();

        // ---- S = Q @ K^T ----
        float sacc[16][4];
#pragma unroll
        for (int nt = 0; nt < 16; nt++)
#pragma unroll
            for (int j = 0; j < 4; j++) sacc[nt][j] = 0.f;

#pragma unroll
        for (int kt = 0; kt < 8; kt++) {
            float4 a4 = Qf[((w * 8 + kt) * 8 + gid) * 4 + tig];
            unsigned af[4] = {__float_as_uint(a4.x), __float_as_uint(a4.y),
                              __float_as_uint(a4.z), __float_as_uint(a4.w)};
#pragma unroll
            for (int nt = 0; nt < 16; nt++) {
                float2 b2 = Kf[(nt * 8 + kt) * 33 + gid * 4 + tig];
                unsigned bf[2] = {__float_as_uint(b2.x), __float_as_uint(b2.y)};
                mma8(sacc[nt], af, bf);
            }
        }

        // ---- masked online softmax (log2 domain) ----
        float rm0 = -INFINITY, rm1 = -INFINITY;
#pragma unroll
        for (int nt = 0; nt < 16; nt++) {
            float mv0 = mk[nt * 8 + tig * 2], mv1 = mk[nt * 8 + tig * 2 + 1];
            float ad0 = (1.f - mv0) * NEG2F, ad1 = (1.f - mv1) * NEG2F;
            sacc[nt][0] = sacc[nt][0] * SCALE2 * mv0 + ad0;
            sacc[nt][1] = sacc[nt][1] * SCALE2 * mv1 + ad1;
            sacc[nt][2] = sacc[nt][2] * SCALE2 * mv0 + ad0;
            sacc[nt][3] = sacc[nt][3] * SCALE2 * mv1 + ad1;
            rm0 = fmaxf(rm0, fmaxf(sacc[nt][0], sacc[nt][1]));
            rm1 = fmaxf(rm1, fmaxf(sacc[nt][2], sacc[nt][3]));
        }
        rm0 = fmaxf(rm0, __shfl_xor_sync(0xffffffffu, rm0, 1));
        rm0 = fmaxf(rm0, __shfl_xor_sync(0xffffffffu, rm0, 2));
        rm1 = fmaxf(rm1, __shfl_xor_sync(0xffffffffu, rm1, 1));
        rm1 = fmaxf(rm1, __shfl_xor_sync(0xffffffffu, rm1, 2));

        float mn0 = fmaxf(m_i[0], rm0), mn1 = fmaxf(m_i[1], rm1);
        float f0 = ex2(m_i[0] - mn0), f1 = ex2(m_i[1] - mn1);
        float s0 = 0.f, s1 = 0.f;
#pragma unroll
        for (int nt = 0; nt < 16; nt++) {
            sacc[nt][0] = ex2(sacc[nt][0] - mn0);
            sacc[nt][1] = ex2(sacc[nt][1] - mn0);
            sacc[nt][2] = ex2(sacc[nt][2] - mn1);
            sacc[nt][3] = ex2(sacc[nt][3] - mn1);
            s0 += sacc[nt][0] + sacc[nt][1];
            s1 += sacc[nt][2] + sacc[nt][3];
        }
        s0 += __shfl_xor_sync(0xffffffffu, s0, 1);
        s0 += __shfl_xor_sync(0xffffffffu, s0, 2);
        s1 += __shfl_xor_sync(0xffffffffu, s1, 1);
        s1 += __shfl_xor_sync(0xffffffffu, s1, 2);
        l_i[0] = l_i[0] * f0 + s0;  m_i[0] = mn0;
        l_i[1] = l_i[1] * f1 + s1;  m_i[1] = mn1;

#pragma unroll
        for (int nt = 0; nt < 8; nt++) {
            oacc[nt][0] *= f0; oacc[nt][1] *= f0;
            oacc[nt][2] *= f1; oacc[nt][3] *= f1;
        }

        // stash P (tf32-rounded) into this warp's private rows
#pragma unroll
        for (int nt = 0; nt < 16; nt++) {
            int c = nt * 8 + tig * 2;
            Ps[r0 * SPP + c]           = __uint_as_float(f2tf(sacc[nt][0]));
            Ps[r0 * SPP + c + 1]       = __uint_as_float(f2tf(sacc[nt][1]));
            Ps[(r0 + 8) * SPP + c]     = __uint_as_float(f2tf(sacc[nt][2]));
            Ps[(r0 + 8) * SPP + c + 1] = __uint_as_float(f2tf(sacc[nt][3]));
        }
        __syncwarp();

        // ---- O += P @ V ----
#pragma unroll
        for (int kt = 0; kt < 16; kt++) {
            unsigned af[4];
            af[0] = __float_as_uint(Ps[r0 * SPP + kt * 8 + tig]);
            af[1] = __float_as_uint(Ps[(r0 + 8) * SPP + kt * 8 + tig]);
            af[2] = __float_as_uint(Ps[r0 * SPP + kt * 8 + 4 + tig]);
            af[3] = __float_as_uint(Ps[(r0 + 8) * SPP + kt * 8 + 4 + tig]);
#pragma unroll
            for (int nt = 0; nt < 8; nt++) {
                float2 b2 = Vf[(nt * 16 + kt) * 33 + gid * 4 + tig];
                unsigned bf[2] = {__float_as_uint(b2.x), __float_as_uint(b2.y)};
                mma8(oacc[nt], af, bf);
            }
        }
        __syncthreads();
    }

    // epilogue: normalize, query-mask, store heads (tf32-rounded)
    int s0r = m0 + r0, s1r = s0r + 8;
    float q0 = mask[(size_t)b * SS + s0r] / l_i[0];
    float q1 = mask[(size_t)b * SS + s1r] / l_i[1];
#pragma unroll
    for (int nt = 0; nt < 8; nt++) {
        int e = h * DVV + nt * 8 + tig * 2;
        float2 v0, v1;
        v0.x = __uint_as_float(f2tf(oacc[nt][0] * q0));
        v0.y = __uint_as_float(f2tf(oacc[nt][1] * q0));
        v1.x = __uint_as_float(f2tf(oacc[nt][2] * q1));
        v1.y = __uint_as_float(f2tf(oacc[nt][3] * q1));
        *(float2*)&g_heads[((size_t)b * SS + s0r) * DD + e] = v0;
        *(float2*)&g_heads[((size_t)b * SS + s1r) * DD + e] = v1;
    }
}

// ---------------------------------------------------------------------------
// Kernel 3: output projection via tf32 mma (unchanged from R2).
// ---------------------------------------------------------------------------
__global__ __launch_bounds__(256) void proj_mma(
    const float* __restrict__ W0, const float* __restrict__ b0,
    float* __restrict__ out)
{
    __shared__ float As[128][40];   // [m][k]
    __shared__ float Bs[128][40];   // [n][k]

    int b = blockIdx.z;
    int m0 = blockIdx.x * 128, n0 = blockIdx.y * 128;
    int tid = threadIdx.x, lane = tid & 31, warp = tid >> 5;
    int wm = warp & 1, wn = warp >> 1;
    int gid = lane >> 2, tig = lane & 3;
    const float* hb = g_heads + (size_t)b * SS * DD;

    float acc[4][4][4];
#pragma unroll
    for (int mt = 0; mt < 4; mt++)
#pragma unroll
        for (int nt = 0; nt < 4; nt++)
#pragma unroll
            for (int j = 0; j < 4; j++) acc[mt][nt][j] = 0.f;

    for (int k0 = 0; k0 < DD; k0 += 32) {
#pragma unroll
        for (int i = tid; i < 128 * 8; i += 256) {
            int mm = i >> 3, k4 = i & 7;
            *(float4*)&As[mm][k4 * 4] =
                *(const float4*)&hb[(size_t)(m0 + mm) * DD + k0 + k4 * 4];
        }
#pragma unroll
        for (int i = tid; i < 128 * 8; i += 256) {
            int nn = i >> 3, k4 = i & 7;
            float4 v = *(const float4*)&W0[(size_t)(n0 + nn) * DD + k0 + k4 * 4];
            v.x = __uint_as_float(f2tf(v.x)); v.y = __uint_as_float(f2tf(v.y));
            v.z = __uint_as_float(f2tf(v.z)); v.w = __uint_as_float(f2tf(v.w));
            *(float4*)&Bs[nn][k4 * 4] = v;
        }
        __syncthreads();
#pragma unroll
        for (int ks = 0; ks < 32; ks += 8) {
            unsigned af[4][4], bf[4][2];
#pragma unroll
            for (int mt = 0; mt < 4; mt++) {
                int m = wm * 64 + mt * 16 + gid;
                af[mt][0] = __float_as_uint(As[m][ks + tig]);
                af[mt][1] = __float_as_uint(As[m + 8][ks + tig]);
                af[mt][2] = __float_as_uint(As[m][ks + 4 + tig]);
                af[mt][3] = __float_as_uint(As[m + 8][ks + 4 + tig]);
            }
#pragma unroll
            for (int nt = 0; nt < 4; nt++) {
                int n = wn * 32 + nt * 8 + gid;
                bf[nt][0] = __float_as_uint(Bs[n][ks + tig]);
                bf[nt][1] = __float_as_uint(Bs[n][ks + 4 + tig]);
            }
#pragma unroll
            for (int mt = 0; mt < 4; mt++)
#pragma unroll
                for (int nt = 0; nt < 4; nt++)
                    mma8(acc[mt][nt], af[mt], bf[nt]);
        }
        __syncthreads();
    }

#pragma unroll
    for (int mt = 0; mt < 4; mt++)
#pragma unroll
        for (int nt = 0; nt < 4; nt++) {
            int n = n0 + wn * 32 + nt * 8 + tig * 2;
            int r = m0 + wm * 64 + mt * 16 + gid;
            float b0v = b0[n], b1v = b0[n + 1];
            size_t c0 = ((size_t)b * DD + n) * SS;
            size_t c1 = c0 + SS;
            out[c0 + r]     = acc[mt][nt][0] + b0v;
            out[c1 + r]     = acc[mt][nt][1] + b1v;
            out[c0 + r + 8] = acc[mt][nt][2] + b0v;
            out[c1 + r + 8] = acc[mt][nt][3] + b1v;
        }
}

// ---------------------------------------------------------------------------
extern "C" void kernel_launch(void* const* d_in, const int* in_sizes, int n_in,
                              void* d_out, int out_size)
{
    const float* x    = (const float*)d_in[0];
    const float* mask = (const float*)d_in[1];
    const float* Wq   = (const float*)d_in[2];
    const float* bq   = (const float*)d_in[3];
    const float* Wk   = (const float*)d_in[4];
    const float* bk   = (const float*)d_in[5];
    const float* Wv   = (const float*)d_in[6];
    const float* bv   = (const float*)d_in[7];
    const float* W0   = (const float*)d_in[8];
    const float* b0   = (const float*)d_in[9];
    float* out = (float*)d_out;

    cudaFuncSetAttribute(attn_mma,
                         cudaFuncAttributeMaxDynamicSharedMemorySize, ATTN_SMEM);

    qkv_mma<<<dim3(SS/128, DD/128, BB*3), 256>>>(x, Wq, bq, Wk, bk, Wv, bv);
    attn_mma<<<dim3(SS/128, BB*HH), 256, ATTN_SMEM>>>(mask);
    proj_mma<<<dim3(SS/128, DD/128, BB), 256>>>(W0, b0, out);
}

// round 4
// speedup vs baseline: 5.1480x; 1.1157x over previous
#include <cuda_runtime.h>
#include <math.h>

#define BB 4
#define SS 2048
#define DD 512
#define HH 8
#define DVV 64
#define NEG_INF_F (-1e30f)

// Scratch (device globals: allocation-free per harness rules)
__device__ float g_q[BB*HH*SS*DVV];
__device__ float g_k[BB*HH*SS*DVV];
__device__ float g_vT[BB*HH*DVV*SS];   // V stored transposed: [b,h,e,s]
__device__ float g_heads[BB*SS*DD];

__device__ __forceinline__ unsigned f2tf(float f) {
    unsigned u;
    asm("cvt.rna.tf32.f32 %0, %1;" : "=r"(u) : "f"(f));
    return u;
}

__device__ __forceinline__ float ex2(float x) {
    float y;
    asm("ex2.approx.ftz.f32 %0, %1;" : "=f"(y) : "f"(x));
    return y;
}

// pack {lo, hi} floats -> bf16x2 register
__device__ __forceinline__ unsigned pbf(float lo, float hi) {
    unsigned r;
    asm("cvt.rn.bf16x2.f32 %0, %1, %2;" : "=r"(r) : "f"(hi), "f"(lo));
    return r;
}

__device__ __forceinline__ void mma8(float* d, const unsigned* a, const unsigned* b) {
    asm volatile(
        "mma.sync.aligned.m16n8k8.row.col.f32.tf32.tf32.f32 "
        "{%0,%1,%2,%3},{%4,%5,%6,%7},{%8,%9},{%0,%1,%2,%3};\n"
        : "+f"(d[0]), "+f"(d[1]), "+f"(d[2]), "+f"(d[3])
        : "r"(a[0]), "r"(a[1]), "r"(a[2]), "r"(a[3]), "r"(b[0]), "r"(b[1]));
}

__device__ __forceinline__ void mma16bf(float* d, const unsigned* a, const unsigned* b) {
    asm volatile(
        "mma.sync.aligned.m16n8k16.row.col.f32.bf16.bf16.f32 "
        "{%0,%1,%2,%3},{%4,%5,%6,%7},{%8,%9},{%0,%1,%2,%3};\n"
        : "+f"(d[0]), "+f"(d[1]), "+f"(d[2]), "+f"(d[3])
        : "r"(a[0]), "r"(a[1]), "r"(a[2]), "r"(a[3]), "r"(b[0]), "r"(b[1]));
}

// ---------------------------------------------------------------------------
// Kernel 1: QKV projection via tf32 mma (unchanged).
// ---------------------------------------------------------------------------
__global__ __launch_bounds__(256) void qkv_mma(
    const float* __restrict__ x,
    const float* __restrict__ Wq, const float* __restrict__ bq,
    const float* __restrict__ Wk, const float* __restrict__ bk,
    const float* __restrict__ Wv, const float* __restrict__ bv)
{
    __shared__ float As[32][136];   // [k][m]
    __shared__ float Bs[128][40];   // [n][k]

    int b = blockIdx.z / 3, w = blockIdx.z % 3;
    const float* W    = (w == 0) ? Wq : (w == 1) ? Wk : Wv;
    const float* bias = (w == 0) ? bq : (w == 1) ? bk : bv;

    int m0 = blockIdx.x * 128, n0 = blockIdx.y * 128;
    int tid = threadIdx.x, lane = tid & 31, warp = tid >> 5;
    int wm = warp & 1, wn = warp >> 1;
    int gid = lane >> 2, tig = lane & 3;
    const float* xb = x + (size_t)b * DD * SS;

    float acc[4][4][4];
#pragma unroll
    for (int mt = 0; mt < 4; mt++)
#pragma unroll
        for (int nt = 0; nt < 4; nt++)
#pragma unroll
            for (int j = 0; j < 4; j++) acc[mt][nt][j] = 0.f;

    for (int k0 = 0; k0 < DD; k0 += 32) {
#pragma unroll
        for (int i = tid; i < 32 * 32; i += 256) {
            int kk = i >> 5, m4 = i & 31;
            float4 v = *(const float4*)&xb[(size_t)(k0 + kk) * SS + m0 + m4 * 4];
            v.x = __uint_as_float(f2tf(v.x)); v.y = __uint_as_float(f2tf(v.y));
            v.z = __uint_as_float(f2tf(v.z)); v.w = __uint_as_float(f2tf(v.w));
            *(float4*)&As[kk][m4 * 4] = v;
        }
#pragma unroll
        for (int i = tid; i < 128 * 8; i += 256) {
            int nn = i >> 3, k4 = i & 7;
            float4 v = *(const float4*)&W[(size_t)(n0 + nn) * DD + k0 + k4 * 4];
            v.x = __uint_as_float(f2tf(v.x)); v.y = __uint_as_float(f2tf(v.y));
            v.z = __uint_as_float(f2tf(v.z)); v.w = __uint_as_float(f2tf(v.w));
            *(float4*)&Bs[nn][k4 * 4] = v;
        }
        __syncthreads();
#pragma unroll
        for (int ks = 0; ks < 32; ks += 8) {
            unsigned af[4][4], bf[4][2];
#pragma unroll
            for (int mt = 0; mt < 4; mt++) {
                int m = wm * 64 + mt * 16 + gid;
                af[mt][0] = __float_as_uint(As[ks + tig][m]);
                af[mt][1] = __float_as_uint(As[ks + tig][m + 8]);
                af[mt][2] = __float_as_uint(As[ks + 4 + tig][m]);
                af[mt][3] = __float_as_uint(As[ks + 4 + tig][m + 8]);
            }
#pragma unroll
            for (int nt = 0; nt < 4; nt++) {
                int n = wn * 32 + nt * 8 + gid;
                bf[nt][0] = __float_as_uint(Bs[n][ks + tig]);
                bf[nt][1] = __float_as_uint(Bs[n][ks + 4 + tig]);
            }
#pragma unroll
            for (int mt = 0; mt < 4; mt++)
#pragma unroll
                for (int nt = 0; nt < 4; nt++)
                    mma8(acc[mt][nt], af[mt], bf[nt]);
        }
        __syncthreads();
    }

    if (w < 2) {
        float* outp = (w == 0) ? g_q : g_k;
#pragma unroll
        for (int mt = 0; mt < 4; mt++)
#pragma unroll
            for (int nt = 0; nt < 4; nt++) {
                int n = n0 + wn * 32 + nt * 8 + tig * 2;
                int r = m0 + wm * 64 + mt * 16 + gid;
                int h = n >> 6, e = n & 63;
                float b0v = bias[n], b1v = bias[n + 1];
                size_t base = (((size_t)b * HH + h) * SS);
                float2 v0, v1;
                v0.x = __uint_as_float(f2tf(acc[mt][nt][0] + b0v));
                v0.y = __uint_as_float(f2tf(acc[mt][nt][1] + b1v));
                v1.x = __uint_as_float(f2tf(acc[mt][nt][2] + b0v));
                v1.y = __uint_as_float(f2tf(acc[mt][nt][3] + b1v));
                *(float2*)&outp[(base + r) * DVV + e]     = v0;
                *(float2*)&outp[(base + r + 8) * DVV + e] = v1;
            }
    } else {
#pragma unroll
        for (int mt = 0; mt < 4; mt++)
#pragma unroll
            for (int nt = 0; nt < 4; nt++) {
                int n = n0 + wn * 32 + nt * 8 + tig * 2;
                int r = m0 + wm * 64 + mt * 16 + gid;
                int h = n >> 6, e = n & 63;
                float b0v = bias[n], b1v = bias[n + 1];
                size_t r0 = (((size_t)b * HH + h) * DVV + e) * SS;
                size_t r1 = r0 + SS;
                g_vT[r0 + r]     = __uint_as_float(f2tf(acc[mt][nt][0] + b0v));
                g_vT[r1 + r]     = __uint_as_float(f2tf(acc[mt][nt][1] + b1v));
                g_vT[r0 + r + 8] = __uint_as_float(f2tf(acc[mt][nt][2] + b0v));
                g_vT[r1 + r + 8] = __uint_as_float(f2tf(acc[mt][nt][3] + b1v));
            }
    }
}

// ---------------------------------------------------------------------------
// Kernel 2: flash attention. QK^T in tf32, PV in bf16 (P direct from S accums,
// no smem P at all). Fragment-native smem for Q/K (fp32) and V (bf16x2).
//   Qf: float4[w8][kt8][gid8][tig4]
//   Kf: float2[(nt*8+kt)][gid][tig], pad 33
//   Vf: uint2 [(j*8+nt)][gid][tig]  (bf16x2 pairs: k-lo 8, k-hi 8)
// smem ~84KB -> 2 CTAs/SM.
// ---------------------------------------------------------------------------
#define QF_FLOATS  (2048 * 4)        // 8192 floats
#define KF_FLOATS  (128 * 33 * 2)    // 8448 floats
#define VF_FLOATS  (2048 * 2)        // 2048 uint2 = 4096 floats
#define ATTN_SMEM  ((QF_FLOATS + KF_FLOATS + VF_FLOATS + 128) * 4)

#define SCALE2 0.1803368801111244f   /* 0.125 * log2(e) */
#define NEG2F  (-1.442695e30f)       /* NEG_INF * log2(e) */

extern __shared__ float smx[];

__global__ __launch_bounds__(256, 2) void attn_mma(const float* __restrict__ mask)
{
    float4* Qf = (float4*)smx;
    float2* Kf = (float2*)(smx + QF_FLOATS);
    uint2*  Vf = (uint2*)(smx + QF_FLOATS + KF_FLOATS);
    float*  mk = smx + QF_FLOATS + KF_FLOATS + VF_FLOATS;

    int bh = blockIdx.y, b = bh >> 3, h = bh & 7;
    int m0 = blockIdx.x * 128;
    int tid = threadIdx.x, lane = tid & 31, w = tid >> 5;
    int gid = lane >> 2, tig = lane & 3;

    const float* qp = g_q  + ((size_t)bh * SS + m0) * DVV;
    const float* kp = g_k  + (size_t)bh * SS * DVV;
    const float* vp = g_vT + (size_t)bh * DVV * SS;

    // Q -> fragment layout (once)
#pragma unroll
    for (int i = tid; i < 2048; i += 256) {
        int ftig = i & 3, fgid = (i >> 2) & 7, fkt = (i >> 5) & 7, fw = i >> 8;
        int r = fw * 16 + fgid, c = fkt * 8 + ftig;
        float4 v;
        v.x = qp[r * DVV + c];
        v.y = qp[(r + 8) * DVV + c];
        v.z = qp[r * DVV + c + 4];
        v.w = qp[(r + 8) * DVV + c + 4];
        Qf[i] = v;
    }

    float m_i[2] = {-INFINITY, -INFINITY}, l_i[2] = {0.f, 0.f};
    float oacc[8][4];
#pragma unroll
    for (int nt = 0; nt < 8; nt++)
#pragma unroll
        for (int j = 0; j < 4; j++) oacc[nt][j] = 0.f;

    int r0 = w * 16 + gid;

    for (int t0 = 0; t0 < SS; t0 += 128) {
        // ---- fill K fragments (tf32 path, fp32 float2) ----
#pragma unroll
        for (int i = tid; i < 1024; i += 256) {
            int fkt = i & 7, n = i >> 3;
            const float* kr = kp + (size_t)(t0 + n) * DVV + fkt * 8;
            float4 lo = *(const float4*)kr, hi = *(const float4*)(kr + 4);
            float2* dst = Kf + ((n >> 3) * 8 + fkt) * 33 + (n & 7) * 4;
            dst[0] = make_float2(lo.x, hi.x);
            dst[1] = make_float2(lo.y, hi.y);
            dst[2] = make_float2(lo.z, hi.z);
            dst[3] = make_float2(lo.w, hi.w);
        }
        // ---- fill V fragments (bf16x2, m16n8k16 B layout) ----
#pragma unroll
        for (int i = tid; i < 512; i += 256) {
            int e = i >> 3, j = i & 7;
            const float* vr = vp + (size_t)e * SS + t0 + j * 16;
            float4 v0 = *(const float4*)vr;
            float4 v1 = *(const float4*)(vr + 4);
            float4 v2 = *(const float4*)(vr + 8);
            float4 v3 = *(const float4*)(vr + 12);
            uint2* dst = Vf + ((j * 8 + (e >> 3)) * 8 + (e & 7)) * 4;
            dst[0] = make_uint2(pbf(v0.x, v0.y), pbf(v2.x, v2.y));
            dst[1] = make_uint2(pbf(v0.z, v0.w), pbf(v2.z, v2.w));
            dst[2] = make_uint2(pbf(v1.x, v1.y), pbf(v3.x, v3.y));
            dst[3] = make_uint2(pbf(v1.z, v1.w), pbf(v3.z, v3.w));
        }
        if (tid < 128) mk[tid] = mask[(size_t)b * SS + t0 + tid];
        __syncthreads();

        // ---- S = Q @ K^T (tf32) ----
        float sacc[16][4];
#pragma unroll
        for (int nt = 0; nt < 16; nt++)
#pragma unroll
            for (int j = 0; j < 4; j++) sacc[nt][j] = 0.f;

#pragma unroll
        for (int kt = 0; kt < 8; kt++) {
            float4 a4 = Qf[((w * 8 + kt) * 8 + gid) * 4 + tig];
            unsigned af[4] = {__float_as_uint(a4.x), __float_as_uint(a4.y),
                              __float_as_uint(a4.z), __float_as_uint(a4.w)};
#pragma unroll
            for (int nt = 0; nt < 16; nt++) {
                float2 b2 = Kf[(nt * 8 + kt) * 33 + gid * 4 + tig];
                unsigned bf[2] = {__float_as_uint(b2.x), __float_as_uint(b2.y)};
                mma8(sacc[nt], af, bf);
            }
        }

        // ---- masked online softmax (log2 domain) ----
        float rm0 = -INFINITY, rm1 = -INFINITY;
#pragma unroll
        for (int nt = 0; nt < 16; nt++) {
            float mv0 = mk[nt * 8 + tig * 2], mv1 = mk[nt * 8 + tig * 2 + 1];
            float ad0 = (1.f - mv0) * NEG2F, ad1 = (1.f - mv1) * NEG2F;
            sacc[nt][0] = sacc[nt][0] * SCALE2 * mv0 + ad0;
            sacc[nt][1] = sacc[nt][1] * SCALE2 * mv1 + ad1;
            sacc[nt][2] = sacc[nt][2] * SCALE2 * mv0 + ad0;
            sacc[nt][3] = sacc[nt][3] * SCALE2 * mv1 + ad1;
            rm0 = fmaxf(rm0, fmaxf(sacc[nt][0], sacc[nt][1]));
            rm1 = fmaxf(rm1, fmaxf(sacc[nt][2], sacc[nt][3]));
        }
        rm0 = fmaxf(rm0, __shfl_xor_sync(0xffffffffu, rm0, 1));
        rm0 = fmaxf(rm0, __shfl_xor_sync(0xffffffffu, rm0, 2));
        rm1 = fmaxf(rm1, __shfl_xor_sync(0xffffffffu, rm1, 1));
        rm1 = fmaxf(rm1, __shfl_xor_sync(0xffffffffu, rm1, 2));

        float mn0 = fmaxf(m_i[0], rm0), mn1 = fmaxf(m_i[1], rm1);
        float f0 = ex2(m_i[0] - mn0), f1 = ex2(m_i[1] - mn1);
        float s0 = 0.f, s1 = 0.f;
#pragma unroll
        for (int nt = 0; nt < 16; nt++) {
            sacc[nt][0] = ex2(sacc[nt][0] - mn0);
            sacc[nt][1] = ex2(sacc[nt][1] - mn0);
            sacc[nt][2] = ex2(sacc[nt][2] - mn1);
            sacc[nt][3] = ex2(sacc[nt][3] - mn1);
            s0 += sacc[nt][0] + sacc[nt][1];
            s1 += sacc[nt][2] + sacc[nt][3];
        }
        s0 += __shfl_xor_sync(0xffffffffu, s0, 1);
        s0 += __shfl_xor_sync(0xffffffffu, s0, 2);
        s1 += __shfl_xor_sync(0xffffffffu, s1, 1);
        s1 += __shfl_xor_sync(0xffffffffu, s1, 2);
        l_i[0] = l_i[0] * f0 + s0;  m_i[0] = mn0;
        l_i[1] = l_i[1] * f1 + s1;  m_i[1] = mn1;

#pragma unroll
        for (int nt = 0; nt < 8; nt++) {
            oacc[nt][0] *= f0; oacc[nt][1] *= f0;
            oacc[nt][2] *= f1; oacc[nt][3] *= f1;
        }

        // ---- O += P @ V (bf16): A fragments come straight from sacc ----
#pragma unroll
        for (int j = 0; j < 8; j++) {
            unsigned af[4];
            af[0] = pbf(sacc[2*j][0],   sacc[2*j][1]);     // row gid,   k 2tig..
            af[1] = pbf(sacc[2*j][2],   sacc[2*j][3]);     // row gid+8
            af[2] = pbf(sacc[2*j+1][0], sacc[2*j+1][1]);   // row gid,   k+8
            af[3] = pbf(sacc[2*j+1][2], sacc[2*j+1][3]);   // row gid+8, k+8
#pragma unroll
            for (int nt = 0; nt < 8; nt++) {
                uint2 b2 = Vf[((j * 8 + nt) * 8 + gid) * 4 + tig];
                unsigned bf[2] = {b2.x, b2.y};
                mma16bf(oacc[nt], af, bf);
            }
        }
        __syncthreads();
    }

    // epilogue: normalize, query-mask, store heads (tf32-rounded)
    int s0r = m0 + r0, s1r = s0r + 8;
    float q0 = mask[(size_t)b * SS + s0r] / l_i[0];
    float q1 = mask[(size_t)b * SS + s1r] / l_i[1];
#pragma unroll
    for (int nt = 0; nt < 8; nt++) {
        int e = h * DVV + nt * 8 + tig * 2;
        float2 v0, v1;
        v0.x = __uint_as_float(f2tf(oacc[nt][0] * q0));
        v0.y = __uint_as_float(f2tf(oacc[nt][1] * q0));
        v1.x = __uint_as_float(f2tf(oacc[nt][2] * q1));
        v1.y = __uint_as_float(f2tf(oacc[nt][3] * q1));
        *(float2*)&g_heads[((size_t)b * SS + s0r) * DD + e] = v0;
        *(float2*)&g_heads[((size_t)b * SS + s1r) * DD + e] = v1;
    }
}

// ---------------------------------------------------------------------------
// Kernel 3: output projection via tf32 mma (unchanged).
// ---------------------------------------------------------------------------
__global__ __launch_bounds__(256) void proj_mma(
    const float* __restrict__ W0, const float* __restrict__ b0,
    float* __restrict__ out)
{
    __shared__ float As[128][40];   // [m][k]
    __shared__ float Bs[128][40];   // [n][k]

    int b = blockIdx.z;
    int m0 = blockIdx.x * 128, n0 = blockIdx.y * 128;
    int tid = threadIdx.x, lane = tid & 31, warp = tid >> 5;
    int wm = warp & 1, wn = warp >> 1;
    int gid = lane >> 2, tig = lane & 3;
    const float* hb = g_heads + (size_t)b * SS * DD;

    float acc[4][4][4];
#pragma unroll
    for (int mt = 0; mt < 4; mt++)
#pragma unroll
        for (int nt = 0; nt < 4; nt++)
#pragma unroll
            for (int j = 0; j < 4; j++) acc[mt][nt][j] = 0.f;

    for (int k0 = 0; k0 < DD; k0 += 32) {
#pragma unroll
        for (int i = tid; i < 128 * 8; i += 256) {
            int mm = i >> 3, k4 = i & 7;
            *(float4*)&As[mm][k4 * 4] =
                *(const float4*)&hb[(size_t)(m0 + mm) * DD + k0 + k4 * 4];
        }
#pragma unroll
        for (int i = tid; i < 128 * 8; i += 256) {
            int nn = i >> 3, k4 = i & 7;
            float4 v = *(const float4*)&W0[(size_t)(n0 + nn) * DD + k0 + k4 * 4];
            v.x = __uint_as_float(f2tf(v.x)); v.y = __uint_as_float(f2tf(v.y));
            v.z = __uint_as_float(f2tf(v.z)); v.w = __uint_as_float(f2tf(v.w));
            *(float4*)&Bs[nn][k4 * 4] = v;
        }
        __syncthreads();
#pragma unroll
        for (int ks = 0; ks < 32; ks += 8) {
            unsigned af[4][4], bf[4][2];
#pragma unroll
            for (int mt = 0; mt < 4; mt++) {
                int m = wm * 64 + mt * 16 + gid;
                af[mt][0] = __float_as_uint(As[m][ks + tig]);
                af[mt][1] = __float_as_uint(As[m + 8][ks + tig]);
                af[mt][2] = __float_as_uint(As[m][ks + 4 + tig]);
                af[mt][3] = __float_as_uint(As[m + 8][ks + 4 + tig]);
            }
#pragma unroll
            for (int nt = 0; nt < 4; nt++) {
                int n = wn * 32 + nt * 8 + gid;
                bf[nt][0] = __float_as_uint(Bs[n][ks + tig]);
                bf[nt][1] = __float_as_uint(Bs[n][ks + 4 + tig]);
            }
#pragma unroll
            for (int mt = 0; mt < 4; mt++)
#pragma unroll
                for (int nt = 0; nt < 4; nt++)
                    mma8(acc[mt][nt], af[mt], bf[nt]);
        }
        __syncthreads();
    }

#pragma unroll
    for (int mt = 0; mt < 4; mt++)
#pragma unroll
        for (int nt = 0; nt < 4; nt++) {
            int n = n0 + wn * 32 + nt * 8 + tig * 2;
            int r = m0 + wm * 64 + mt * 16 + gid;
            float b0v = b0[n], b1v = b0[n + 1];
            size_t c0 = ((size_t)b * DD + n) * SS;
            size_t c1 = c0 + SS;
            out[c0 + r]     = acc[mt][nt][0] + b0v;
            out[c1 + r]     = acc[mt][nt][1] + b1v;
            out[c0 + r + 8] = acc[mt][nt][2] + b0v;
            out[c1 + r + 8] = acc[mt][nt][3] + b1v;
        }
}

// ---------------------------------------------------------------------------
extern "C" void kernel_launch(void* const* d_in, const int* in_sizes, int n_in,
                              void* d_out, int out_size)
{
    const float* x    = (const float*)d_in[0];
    const float* mask = (const float*)d_in[1];
    const float* Wq   = (const float*)d_in[2];
    const float* bq   = (const float*)d_in[3];
    const float* Wk   = (const float*)d_in[4];
    const float* bk   = (const float*)d_in[5];
    const float* Wv   = (const float*)d_in[6];
    const float* bv   = (const float*)d_in[7];
    const float* W0   = (const float*)d_in[8];
    const float* b0   = (const float*)d_in[9];
    float* out = (float*)d_out;

    cudaFuncSetAttribute(attn_mma,
                         cudaFuncAttributeMaxDynamicSharedMemorySize, ATTN_SMEM);

    qkv_mma<<<dim3(SS/128, DD/128, BB*3), 256>>>(x, Wq, bq, Wk, bk, Wv, bv);
    attn_mma<<<dim3(SS/128, BB*HH), 256, ATTN_SMEM>>>(mask);
    proj_mma<<<dim3(SS/128, DD/128, BB), 256>>>(W0, b0, out);
}